// round 16
// baseline (speedup 1.0000x reference)
#include <cuda_runtime.h>
#include <cstdint>

// GRU teacher-forced NLL, B=8192, S=2048, H=8, IN_DIM=4, MAX_COUNT=10.
// R14 base (350.9us): 2 lanes/element, packed FFMA2, tanh.approx activations.
// R15: persistent duplicated h-pairs. dup2() MOVs dominated overhead (~32/step);
//      now h is kept as dup-pairs (myh2/oh2) built ONCE per step and reused by
//      both the logit matvec (this step) and the hidden matvec (next step).
//      Bit-identical arithmetic -> rel_err must stay 1.034058e-07.
//   sigmoid(x) = 0.5*tanh(x/2) + 0.5   (0.5 pre-folded into gate weights/tables)
//   tanh(x)    = tanh.approx(x)
// Softmax in log2 domain, no max shift (logits provably bounded).

#define NBLK 128
#define NTHR 128
#define SSTEPS 2048

typedef unsigned long long u64;

__device__ float g_partials[NBLK];

__device__ __forceinline__ float fast_ex2(float x) {
    float y; asm("ex2.approx.f32 %0, %1;" : "=f"(y) : "f"(x)); return y;
}
__device__ __forceinline__ float fast_lg2(float x) {
    float y; asm("lg2.approx.f32 %0, %1;" : "=f"(y) : "f"(x)); return y;
}
__device__ __forceinline__ float fast_tanh(float x) {
    float y; asm("tanh.approx.f32 %0, %1;" : "=f"(y) : "f"(x)); return y;
}
__device__ __forceinline__ u64 pack2(float lo, float hi) {
    u64 r; asm("mov.b64 %0, {%1, %2};" : "=l"(r) : "f"(lo), "f"(hi)); return r;
}
__device__ __forceinline__ void unpack2(float& lo, float& hi, u64 v) {
    asm("mov.b64 {%0, %1}, %2;" : "=f"(lo), "=f"(hi) : "l"(v));
}
__device__ __forceinline__ u64 fma2(u64 a, u64 b, u64 c) {
    u64 d; asm("fma.rn.f32x2 %0, %1, %2, %3;" : "=l"(d) : "l"(a), "l"(b), "l"(c));
    return d;
}

__global__ __launch_bounds__(NTHR) void gru_kernel(
    const int* __restrict__ x,
    const float* __restrict__ Wir, const float* __restrict__ bir,
    const float* __restrict__ Wiz, const float* __restrict__ biz,
    const float* __restrict__ Win, const float* __restrict__ bin_,
    const float* __restrict__ Whr, const float* __restrict__ bhr,
    const float* __restrict__ Whz, const float* __restrict__ bhz,
    const float* __restrict__ Whn, const float* __restrict__ bhn,
    const float* __restrict__ Wout, const float* __restrict__ bout)
{
    __shared__ __align__(16) float tbl[240];   // [gate(3)][count(10)][unit(8)]
    __shared__ float wsum[4];

    const int tid  = threadIdx.x;
    const int half = tid & 1;
    const int e    = blockIdx.x * (NTHR / 2) + (tid >> 1);
    const float LOG2E = 1.4426950408889634f;

    // ---- build input tables: ALL 240 entries ----
    // r/z tables hold pre/2 (sigmoid-as-tanh); n table holds pre unscaled.
    for (int idx = tid; idx < 240; idx += NTHR) {
        int g = idx / 80, rem = idx % 80, c = rem / 8, i = rem % 8;
        const float* Wi = (g == 0) ? Wir : (g == 1) ? Wiz : Win;
        const float* bi = (g == 0) ? bir : (g == 1) ? biz : bin_;
        float v = bi[i];
        if (g == 0) v += bhr[i];
        if (g == 1) v += bhz[i];
        #pragma unroll
        for (int k = 0; k < 4; k++)
            if (c & (1 << (3 - k))) v += Wi[i * 4 + k];   // MSB-first bits
        if (g < 2) v *= 0.5f;
        tbl[idx] = v;
    }

    // ---- packed per-thread weights (columns permuted: my units first) ----
    u64 wr2[2][8], wz2[2][8], wn2[2][8], bhn2[2];
    #pragma unroll
    for (int p = 0; p < 2; p++) {
        int r0 = half * 4 + 2 * p, r1 = r0 + 1;
        bhn2[p] = pack2(bhn[r0], bhn[r1]);
        #pragma unroll
        for (int jj = 0; jj < 8; jj++) {
            int col = (jj + half * 4) & 7;
            wr2[p][jj] = pack2(0.5f * Whr[r0 * 8 + col], 0.5f * Whr[r1 * 8 + col]);
            wz2[p][jj] = pack2(0.5f * Whz[r0 * 8 + col], 0.5f * Whz[r1 * 8 + col]);
            wn2[p][jj] = pack2(Whn[r0 * 8 + col], Whn[r1 * 8 + col]);
        }
    }
    // Logit weights: classes half*5 + {0..4}; (0,1),(2,3) packed, 4 scalar.
    u64 wo01[8], wo23[8];
    float wo4[8];
    {
        int c0 = half * 5;
        #pragma unroll
        for (int jj = 0; jj < 8; jj++) {
            int col = (jj + half * 4) & 7;
            wo01[jj] = pack2(LOG2E * Wout[(c0 + 0) * 8 + col], LOG2E * Wout[(c0 + 1) * 8 + col]);
            wo23[jj] = pack2(LOG2E * Wout[(c0 + 2) * 8 + col], LOG2E * Wout[(c0 + 3) * 8 + col]);
            wo4[jj]  = LOG2E * Wout[(c0 + 4) * 8 + col];
        }
    }
    u64 bo01, bo23; float bo4;
    {
        int c0 = half * 5;
        bo01 = pack2(LOG2E * bout[c0 + 0], LOG2E * bout[c0 + 1]);
        bo23 = pack2(LOG2E * bout[c0 + 2], LOG2E * bout[c0 + 3]);
        bo4  = LOG2E * bout[c0 + 4];
    }
    __syncthreads();

    const ulonglong2* t2 = (const ulonglong2*)tbl;   // 16B granules, pair layout

    // h state: scalar copies for the activation update + persistent dup-pairs
    // consumed by BOTH the logit matvec (this step) and hidden matvec (next).
    float myh[4] = {0.f, 0.f, 0.f, 0.f};
    u64 myh2[4], oh2[4];
    #pragma unroll
    for (int u = 0; u < 4; u++) { myh2[u] = pack2(0.f, 0.f); oh2[u] = pack2(0.f, 0.f); }
    float loss2 = 0.f;

    const int4* row4 = (const int4*)(x + (size_t)e * SSTEPS);
    int4 cur = row4[0];
    int prev_c = 0;

    #pragma unroll 1
    for (int blk = 0; blk < SSTEPS / 4; blk++) {
        int4 nxt = cur;
        if (blk < SSTEPS / 4 - 1) nxt = row4[blk + 1];
        int tg0 = cur.x, tg1 = cur.y, tg2 = cur.z, tg3 = cur.w;
        #pragma unroll
        for (int s = 0; s < 4; s++) {
            const int c   = prev_c;
            const int tgt = (s == 0) ? tg0 : (s == 1) ? tg1 : (s == 2) ? tg2 : tg3;
            prev_c = tgt;

            // input tables for my 4 units (packed-pair form)
            const int ti = c * 2 + half;
            ulonglong2 trv = t2[ti];
            ulonglong2 tzv = t2[20 + ti];
            ulonglong2 tnv = t2[40 + ti];

            u64 ar2[2] = {trv.x, trv.y};
            u64 az2[2] = {tzv.x, tzv.y};
            u64 an2[2] = {bhn2[0], bhn2[1]};

            // hidden matvec: packed FFMA2 on persistent dup-pairs (no dup moves)
            #pragma unroll
            for (int j = 0; j < 4; j++) {
                u64 h2 = myh2[j];
                ar2[0] = fma2(wr2[0][j], h2, ar2[0]);
                ar2[1] = fma2(wr2[1][j], h2, ar2[1]);
                az2[0] = fma2(wz2[0][j], h2, az2[0]);
                az2[1] = fma2(wz2[1][j], h2, az2[1]);
                an2[0] = fma2(wn2[0][j], h2, an2[0]);
                an2[1] = fma2(wn2[1][j], h2, an2[1]);
            }
            #pragma unroll
            for (int j = 0; j < 4; j++) {
                u64 h2 = oh2[j];
                ar2[0] = fma2(wr2[0][4 + j], h2, ar2[0]);
                ar2[1] = fma2(wr2[1][4 + j], h2, ar2[1]);
                az2[0] = fma2(wz2[0][4 + j], h2, az2[0]);
                az2[1] = fma2(wz2[1][4 + j], h2, az2[1]);
                an2[0] = fma2(wn2[0][4 + j], h2, an2[0]);
                an2[1] = fma2(wn2[1][4 + j], h2, an2[1]);
            }

            float ar[4], az[4], an[4], tn[4];
            unpack2(ar[0], ar[1], ar2[0]); unpack2(ar[2], ar[3], ar2[1]);
            unpack2(az[0], az[1], az2[0]); unpack2(az[2], az[3], az2[1]);
            unpack2(an[0], an[1], an2[0]); unpack2(an[2], an[3], an2[1]);
            unpack2(tn[0], tn[1], tnv.x);  unpack2(tn[2], tn[3], tnv.y);

            // activations via tanh.approx (3 MUFU/unit), then rebuild dup-pairs
            #pragma unroll
            for (int u = 0; u < 4; u++) {
                float trh  = fast_tanh(ar[u]);
                float tzh  = fast_tanh(az[u]);
                float npre = fmaf(0.5f, fmaf(trh, an[u], an[u]), tn[u]);
                float n    = fast_tanh(npre);
                float z    = fmaf(0.5f, tzh, 0.5f);
                float hn   = fmaf(z, myh[u] - n, n);
                myh[u]  = hn;
                myh2[u] = pack2(hn, hn);
                float os = __shfl_xor_sync(0xffffffffu, hn, 1);
                oh2[u]  = pack2(os, os);
            }

            // logits (log2-scaled): packed class pairs (0,1),(2,3) + scalar 4
            u64 l01 = bo01, l23 = bo23;
            float l4 = bo4;
            #pragma unroll
            for (int j = 0; j < 4; j++) {
                u64 h2 = myh2[j];
                float hs;
                { float hi_; unpack2(hs, hi_, h2); }
                l01 = fma2(wo01[j], h2, l01);
                l23 = fma2(wo23[j], h2, l23);
                l4  = fmaf(wo4[j], myh[j], l4);
            }
            #pragma unroll
            for (int j = 0; j < 4; j++) {
                u64 h2 = oh2[j];
                float os;
                { float hi_; unpack2(os, hi_, h2); }
                l01 = fma2(wo01[4 + j], h2, l01);
                l23 = fma2(wo23[4 + j], h2, l23);
                l4  = fmaf(wo4[4 + j], os, l4);
            }
            float l[5];
            unpack2(l[0], l[1], l01);
            unpack2(l[2], l[3], l23);
            l[4] = l4;

            // log-softmax NLL across the lane pair, log2 domain, no max shift
            float esum = fast_ex2(l[0]);
            esum += fast_ex2(l[1]);
            esum += fast_ex2(l[2]);
            esum += fast_ex2(l[3]);
            esum += fast_ex2(l[4]);
            esum += __shfl_xor_sync(0xffffffffu, esum, 1);
            float lse2 = fast_lg2(esum);

            // target logit: zero-masked contribution, summed across the pair
            int k = tgt - half * 5;
            float contrib = 0.f;
            contrib = (k == 0) ? l[0] : contrib;
            contrib = (k == 1) ? l[1] : contrib;
            contrib = (k == 2) ? l[2] : contrib;
            contrib = (k == 3) ? l[3] : contrib;
            contrib = (k == 4) ? l[4] : contrib;
            float lt = contrib + __shfl_xor_sync(0xffffffffu, contrib, 1);

            loss2 += lse2 - lt;   // nll * log2e (both lanes identical)
        }
        cur = nxt;
    }

    // ---- deterministic block reduction ----
    #pragma unroll
    for (int off = 16; off; off >>= 1)
        loss2 += __shfl_xor_sync(0xffffffffu, loss2, off);
    if ((tid & 31) == 0) wsum[tid >> 5] = loss2;
    __syncthreads();
    if (tid == 0)
        g_partials[blockIdx.x] = wsum[0] + wsum[1] + wsum[2] + wsum[3];
}

__global__ void finalize_kernel(float* __restrict__ out)
{
    __shared__ float s[4];
    int tid = threadIdx.x;
    float v = g_partials[tid];
    #pragma unroll
    for (int off = 16; off; off >>= 1)
        v += __shfl_xor_sync(0xffffffffu, v, off);
    if ((tid & 31) == 0) s[tid >> 5] = v;
    __syncthreads();
    if (tid == 0) {
        // each element counted twice (both lanes), log2 units -> nats, mean over B*S
        const float scale = (float)(0.6931471805599453 / (2.0 * 8192.0 * 2048.0));
        out[0] = (s[0] + s[1] + s[2] + s[3]) * scale;
    }
}

extern "C" void kernel_launch(void* const* d_in, const int* in_sizes, int n_in,
                              void* d_out, int out_size)
{
    (void)in_sizes; (void)n_in; (void)out_size;
    const int*   x    = (const int*)  d_in[0];
    const float* Wir  = (const float*)d_in[1];
    const float* bir  = (const float*)d_in[2];
    const float* Wiz  = (const float*)d_in[3];
    const float* biz  = (const float*)d_in[4];
    const float* Win  = (const float*)d_in[5];
    const float* bin_ = (const float*)d_in[6];
    const float* Whr  = (const float*)d_in[7];
    const float* bhr  = (const float*)d_in[8];
    const float* Whz  = (const float*)d_in[9];
    const float* bhz  = (const float*)d_in[10];
    const float* Whn  = (const float*)d_in[11];
    const float* bhn  = (const float*)d_in[12];
    const float* Wout = (const float*)d_in[13];
    const float* bout = (const float*)d_in[14];

    gru_kernel<<<NBLK, NTHR>>>(x, Wir, bir, Wiz, biz, Win, bin_,
                               Whr, bhr, Whz, bhz, Whn, bhn, Wout, bout);
    finalize_kernel<<<1, NBLK>>>((float*)d_out);
}